// round 13
// baseline (speedup 1.0000x reference)
#include <cuda_runtime.h>
#include <cuda_fp16.h>
#include <math.h>

#define NV  100000
#define EE  1600000
#define FIN 512
#define D1  64
#define H1N 8
#define D2  16
#define SCAN_CH 1024
#define SCAN_NB ((NV + SCAN_CH - 1) / SCAN_CH)   // 98

typedef unsigned long long u64;

// ---- packed f32x2 helpers ----
__device__ __forceinline__ void ffma2(u64& d, u64 a, u64 b) {
    asm("fma.rn.f32x2 %0, %1, %2, %0;" : "+l"(d) : "l"(a), "l"(b));
}
__device__ __forceinline__ u64 pack2(float x, float y) {
    u64 r;
    asm("mov.b64 %0, {%1, %2};" : "=l"(r) : "f"(x), "f"(y));
    return r;
}
__device__ __forceinline__ void unpack2(u64 v, float& x, float& y) {
    asm("mov.b64 {%0, %1}, %2;" : "=f"(x), "=f"(y) : "l"(v));
}

// ---- fp16 MMA helpers ----
__device__ __forceinline__ void ldsm4(unsigned* r, const void* p) {
    unsigned addr = (unsigned)__cvta_generic_to_shared(p);
    asm volatile("ldmatrix.sync.aligned.m8n8.x4.shared.b16 {%0,%1,%2,%3}, [%4];"
                 : "=r"(r[0]), "=r"(r[1]), "=r"(r[2]), "=r"(r[3]) : "r"(addr));
}
__device__ __forceinline__ void mma_f16(float* c, const unsigned* a, const unsigned* b) {
    asm volatile(
        "mma.sync.aligned.m16n8k16.row.col.f32.f16.f16.f32 "
        "{%0,%1,%2,%3}, {%4,%5,%6,%7}, {%8,%9}, {%0,%1,%2,%3};"
        : "+f"(c[0]), "+f"(c[1]), "+f"(c[2]), "+f"(c[3])
        : "r"(a[0]), "r"(a[1]), "r"(a[2]), "r"(a[3]), "r"(b[0]), "r"(b[1]));
}

// ---- scratch (device globals; no allocations allowed) ----
__device__ __half g_hp16[(size_t)NV * D1];   // x @ W1, fp16 (gather payload)
__device__ float  g_al1s[NV * H1N];
__device__ float  g_al1d[NV * H1N];
__device__ __half g_hp2h[(size_t)NV * D2];   // h1 @ W2, fp16 (gather payload)
__device__ float  g_al2s[NV];
__device__ float  g_al2d[NV];
__device__ __half g_W16[D1 * FIN * 2];       // [n][k] hi at k, lo at 512+k
__device__ int    g_cnt[NV];   // INVARIANT: all-zero at launch entry & exit
                               // (khist adds deg, kfill counts back to 0)
__device__ int    g_off[NV + 1];
__device__ int    g_esrc[EE];
__device__ int    g_blk[SCAN_NB];
__device__ int    g_blkoff[SCAN_NB];
__device__ int    g_done;                    // last-block flag (self-resetting)

// ---------------- initW: split W1 into fp16 hi/lo (feeds kgemm1) ------------
__global__ void kinitW(const float* __restrict__ W1) {
    int t = blockIdx.x * blockDim.x + threadIdx.x;
    if (t < FIN * D1) {
        int k = t >> 6, n = t & 63;
        float w = W1[t];
        __half h = __float2half_rn(w);
        float lo = w - __half2float(h);
        g_W16[n * (FIN * 2) + k]       = h;
        g_W16[n * (FIN * 2) + FIN + k] = __float2half_rn(lo);
    }
}

// ---------------- CSR: histogram of dst ----------------
__global__ void khist(const int* __restrict__ dst) {
    int e = blockIdx.x * blockDim.x + threadIdx.x;
    if (e < EE) atomicAdd(&g_cnt[dst[e]], 1);
}

// ---------------- CSR: fused scan stage 1+2 ----------------
__global__ __launch_bounds__(256) void kscan12() {
    __shared__ int wsum[8];
    __shared__ int isLast;
    __shared__ int sm[128];
    int b = blockIdx.x, t = threadIdx.x;
    int base = b * SCAN_CH + t * 4;
    int s = 0;
#pragma unroll
    for (int l = 0; l < 4; l++) s += (base + l < NV) ? g_cnt[base + l] : 0;
#pragma unroll
    for (int off = 16; off >= 1; off >>= 1) s += __shfl_down_sync(0xffffffffu, s, off);
    if ((t & 31) == 0) wsum[t >> 5] = s;
    __syncthreads();
    if (t == 0) {
        int tot = 0;
#pragma unroll
        for (int w = 0; w < 8; w++) tot += wsum[w];
        g_blk[b] = tot;
        __threadfence();
        int v = atomicAdd(&g_done, 1);
        isLast = (v == SCAN_NB - 1);
        if (isLast) g_done = 0;
    }
    __syncthreads();
    if (!isLast) return;
    __threadfence();
    int v = (t < SCAN_NB) ? *(volatile int*)&g_blk[t] : 0;
    if (t < 128) sm[t] = v;
    __syncthreads();
    for (int off = 1; off < 128; off <<= 1) {
        int y = (t >= off && t < 128) ? sm[t - off] : 0;
        __syncthreads();
        if (t < 128) sm[t] += y;
        __syncthreads();
    }
    if (t < SCAN_NB) g_blkoff[t] = sm[t] - v;
}

// ---------------- CSR: scan stage 3 ----------------
__global__ __launch_bounds__(256) void kscan3() {
    __shared__ int wsum[8];
    int b = blockIdx.x, t = threadIdx.x;
    int lane = t & 31, w = t >> 5;
    int base = b * SCAN_CH + t * 4;
    int v[4];
#pragma unroll
    for (int l = 0; l < 4; l++) v[l] = (base + l < NV) ? g_cnt[base + l] : 0;
    int s4 = v[0] + v[1] + v[2] + v[3];
    int x = s4;
#pragma unroll
    for (int off = 1; off < 32; off <<= 1) {
        int y = __shfl_up_sync(0xffffffffu, x, off);
        if (lane >= off) x += y;
    }
    if (lane == 31) wsum[w] = x;
    __syncthreads();
    if (t < 8) {
        int y = wsum[t];
#pragma unroll
        for (int off = 1; off < 8; off <<= 1) {
            int z = __shfl_up_sync(0x000000ffu, y, off);
            if (t >= off) y += z;
        }
        wsum[t] = y;
    }
    __syncthreads();
    int run = g_blkoff[b] + (x - s4) + (w > 0 ? wsum[w - 1] : 0);
#pragma unroll
    for (int l = 0; l < 4; l++) {
        if (base + l < NV) g_off[base + l] = run;
        run += v[l];
    }
    if (b == 0 && t == 0) g_off[NV] = EE;
}

// ---------------- CSR: fill (countdown on g_cnt → restores zeros) -----------
__global__ void kfill(const int* __restrict__ src, const int* __restrict__ dst) {
    int e = blockIdx.x * blockDim.x + threadIdx.x;
    if (e >= EE) return;
    int d = dst[e];
    int slot = atomicAdd(&g_cnt[d], -1) - 1;   // deg-1 .. 0; ends at exactly 0
    g_esrc[g_off[d] + slot] = src[e];
}

// ---------------- GEMM1: 2-term fp16 split MMA, x prefetch distance 2 -------
__global__ __launch_bounds__(256, 2) void kgemm1(const float* __restrict__ x,
                                                 const float* __restrict__ a1s,
                                                 const float* __restrict__ a1d) {
    __shared__ __half Ah[128][40];    // hi only, stride 40
    __shared__ __half Bh[64][72];     // hi|lo, stride 72

    const int tid   = threadIdx.x;
    const int lane  = tid & 31;
    const int wid   = tid >> 5;
    const int g     = lane >> 2;
    const int tg    = lane & 3;
    const int warpM = wid & 3;
    const int warpN = wid >> 2;
    const int row0  = blockIdx.x * 128;

    const int lrow  = lane & 15;
    const int lcolA = (lane >> 4) * 8;
    const int brow  = (lane & 7) + ((lane >> 4) * 8);
    const int bcol  = ((lane >> 3) & 1) * 8;

    float acc[2][4][4];
#pragma unroll
    for (int mi = 0; mi < 2; mi++)
#pragma unroll
        for (int ni = 0; ni < 4; ni++)
#pragma unroll
            for (int q = 0; q < 4; q++) acc[mi][ni][q] = 0.f;

    const float4 z4 = make_float4(0.f, 0.f, 0.f, 0.f);
    float4 rx[2][4];
    uint4  rb[2];

    // per-thread x source pointer (row fixed per l; only k advances)
    int xr[4];  bool xok[4];
#pragma unroll
    for (int l = 0; l < 4; l++) {
        int f = l * 256 + tid;
        xr[l]  = f >> 3;
        xok[l] = (row0 + xr[l]) < NV;
    }
    const int xc4 = (tid & 7) * 4;

    // preload x tiles 0,1 and B tile 0
#pragma unroll
    for (int l = 0; l < 4; l++)
        rx[0][l] = xok[l] ? __ldcs((const float4*)(x + (size_t)(row0 + xr[l]) * FIN + xc4)) : z4;
#pragma unroll
    for (int l = 0; l < 4; l++)
        rx[1][l] = xok[l] ? __ldcs((const float4*)(x + (size_t)(row0 + xr[l]) * FIN + 32 + xc4)) : z4;
#pragma unroll
    for (int l = 0; l < 2; l++) {
        int f = l * 256 + tid, n = f >> 3, q = f & 7;
        int off = n * (FIN * 2) + ((q < 4) ? (q * 8) : (FIN + (q - 4) * 8));
        rb[l] = *(const uint4*)(g_W16 + off);
    }

    const int NT = FIN / 32;   // 16
    for (int it = 0; it < NT; it++) {
        const int cur = it & 1;
        // store A (fp16 round) + B
#pragma unroll
        for (int l = 0; l < 4; l++) {
            int c = ((l * 256 + tid) & 7) * 4;
            float4 v = rx[cur][l];
            *(__half2*)&Ah[xr[l]][c]     = __floats2half2_rn(v.x, v.y);
            *(__half2*)&Ah[xr[l]][c + 2] = __floats2half2_rn(v.z, v.w);
        }
#pragma unroll
        for (int l = 0; l < 2; l++) {
            int f = l * 256 + tid, n = f >> 3, q = f & 7;
            *(uint4*)&Bh[n][q * 8] = rb[l];
        }
        __syncthreads();

        // prefetch x tile it+2 (distance 2) and B tile it+1 (distance 1)
        if (it + 2 < NT) {
            int kn = (it + 2) * 32;
#pragma unroll
            for (int l = 0; l < 4; l++)
                rx[cur][l] = xok[l]
                    ? __ldcs((const float4*)(x + (size_t)(row0 + xr[l]) * FIN + kn + xc4)) : z4;
        }
        if (it + 1 < NT) {
            int kn = (it + 1) * 32;
#pragma unroll
            for (int l = 0; l < 2; l++) {
                int f = l * 256 + tid, n = f >> 3, q = f & 7;
                int off = n * (FIN * 2) + ((q < 4) ? (kn + q * 8) : (FIN + kn + (q - 4) * 8));
                rb[l] = *(const uint4*)(g_W16 + off);
            }
        }

#pragma unroll
        for (int s = 0; s < 2; s++) {
            unsigned ah[2][4], bh[4][2], bl[4][2];
#pragma unroll
            for (int mi = 0; mi < 2; mi++) {
                const __half* pa = &Ah[warpM * 32 + mi * 16 + lrow][s * 16 + lcolA];
                ldsm4(ah[mi], pa);
            }
#pragma unroll
            for (int a = 0; a < 2; a++) {
                const __half* pb = &Bh[warpN * 32 + a * 16 + brow][s * 16 + bcol];
                unsigned t4[4];
                ldsm4(t4, pb);
                bh[2 * a][0] = t4[0]; bh[2 * a][1] = t4[1];
                bh[2 * a + 1][0] = t4[2]; bh[2 * a + 1][1] = t4[3];
                ldsm4(t4, pb + 32);
                bl[2 * a][0] = t4[0]; bl[2 * a][1] = t4[1];
                bl[2 * a + 1][0] = t4[2]; bl[2 * a + 1][1] = t4[3];
            }
#pragma unroll
            for (int mi = 0; mi < 2; mi++)
#pragma unroll
                for (int ni = 0; ni < 4; ni++) {
                    mma_f16(acc[mi][ni], ah[mi], bl[ni]);
                    mma_f16(acc[mi][ni], ah[mi], bh[ni]);
                }
        }
        __syncthreads();
    }

    // epilogue: store hp1 (fp16) + fused attention projections (fp32)
    float2 as2[4], ad2[4];
#pragma unroll
    for (int ni = 0; ni < 4; ni++) {
        int h = warpN * 4 + ni;
        as2[ni] = make_float2(a1s[h * 8 + 2 * tg], a1s[h * 8 + 2 * tg + 1]);
        ad2[ni] = make_float2(a1d[h * 8 + 2 * tg], a1d[h * 8 + 2 * tg + 1]);
    }
#pragma unroll
    for (int mi = 0; mi < 2; mi++)
#pragma unroll
        for (int rh = 0; rh < 2; rh++) {
            int row = row0 + warpM * 32 + mi * 16 + rh * 8 + g;
            bool ok = row < NV;
#pragma unroll
            for (int ni = 0; ni < 4; ni++) {
                float c0 = acc[mi][ni][rh * 2], c1 = acc[mi][ni][rh * 2 + 1];
                if (ok) {
                    int col = warpN * 32 + ni * 8 + 2 * tg;
                    *(__half2*)(g_hp16 + (size_t)row * D1 + col) = __floats2half2_rn(c0, c1);
                }
                float sp = c0 * as2[ni].x + c1 * as2[ni].y;
                float dp = c0 * ad2[ni].x + c1 * ad2[ni].y;
                sp += __shfl_xor_sync(0xffffffffu, sp, 1);
                sp += __shfl_xor_sync(0xffffffffu, sp, 2);
                dp += __shfl_xor_sync(0xffffffffu, dp, 1);
                dp += __shfl_xor_sync(0xffffffffu, dp, 2);
                if (ok && tg == ni) {
                    g_al1s[row * H1N + warpN * 4 + ni] = sp;
                    g_al1d[row * H1N + warpN * 4 + ni] = dp;
                }
            }
        }
}

// ---------------- layer-1 aggregation + FUSED GEMM2 + al2 -------------------
__global__ __launch_bounds__(256) void kagg1(const float* __restrict__ b1,
                                             const float* __restrict__ W2,
                                             const float* __restrict__ a2s,
                                             const float* __restrict__ a2d) {
    __shared__ u64   W2p[D1 * 9];
    __shared__ float A2s[D2], A2d[D2];
    {
        int tid = threadIdx.x;
        for (int i = tid; i < D1 * 8; i += 256) {
            int k = i >> 3, j = i & 7;
            W2p[k * 9 + j] = pack2(W2[k * D2 + 2 * j], W2[k * D2 + 2 * j + 1]);
        }
        if (tid < D2)           A2s[tid] = a2s[tid];
        else if (tid < 2 * D2)  A2d[tid - D2] = a2d[tid - D2];
        __syncthreads();
    }

    int gw = (blockIdx.x * blockDim.x + threadIdx.x) >> 5;
    if (gw >= NV) return;
    const int d    = gw;
    const int lane = threadIdx.x & 31;
    const int grp  = lane >> 3;
    const int gh   = lane & 7;
    const int hsel = lane >> 2;

    const float ald = g_al1d[d * H1N + gh];
    float accx = 0.f, accy = 0.f, den = 0.f;

    {
        float w = 0.f;
        if (grp == 0) {
            float v = g_al1s[d * H1N + gh] + ald;
            v = (v > 0.f) ? v : 0.2f * v;
            w = __expf(v);
            den += w;
        }
        float wl = __shfl_sync(0xffffffffu, w, hsel);
        float2 hv = __half22float2(*(const __half2*)&g_hp16[(size_t)d * D1 + 2 * lane]);
        accx = fmaf(hv.x, wl, accx);
        accy = fmaf(hv.y, wl, accy);
    }

    const int beg = g_off[d], end = g_off[d + 1];
    for (int j = beg; j < end; j += 32) {
        int idx = j + lane;
        int sv  = g_esrc[(idx < end) ? idx : (end - 1)];
        int m   = end - j; if (m > 32) m = 32;
        for (int k = 0; k < m; k += 4) {
            int ke = k + grp;
            int kc = (ke < m) ? ke : (m - 1);
            int s_my = __shfl_sync(0xffffffffu, sv, kc);
            float w = 0.f;
            if (ke < m) {
                float v = g_al1s[s_my * H1N + gh] + ald;
                v = (v > 0.f) ? v : 0.2f * v;
                w = __expf(v);
                den += w;
            }
#pragma unroll
            for (int e = 0; e < 4; e++) {
                int kk  = k + e;
                int kcl = (kk < m) ? kk : (m - 1);
                int s_e = __shfl_sync(0xffffffffu, sv, kcl);
                float wl = __shfl_sync(0xffffffffu, w, e * 8 + hsel);
                float2 hv = __half22float2(
                    *(const __half2*)&g_hp16[(size_t)s_e * D1 + 2 * lane]);
                accx = fmaf(hv.x, wl, accx);
                accy = fmaf(hv.y, wl, accy);
            }
        }
    }

    den += __shfl_xor_sync(0xffffffffu, den, 8);
    den += __shfl_xor_sync(0xffffffffu, den, 16);
    float dl = __shfl_sync(0xffffffffu, den, hsel);

    float v0 = accx / dl + b1[2 * lane];
    float v1 = accy / dl + b1[2 * lane + 1];
    v0 = (v0 > 0.f) ? v0 : expm1f(v0);
    v1 = (v1 > 0.f) ? v1 : expm1f(v1);

    // ---- fused GEMM2 ----
    u64 P[8];
    u64 a0 = pack2(v0, v0), a1 = pack2(v1, v1);
    const u64* w0 = &W2p[(2 * lane) * 9];
    const u64* w1 = &W2p[(2 * lane + 1) * 9];
#pragma unroll
    for (int j = 0; j < 8; j++) {
        P[j] = 0ULL;
        ffma2(P[j], a0, w0[j]);
        ffma2(P[j], a1, w1[j]);
    }
    float p[16];
#pragma unroll
    for (int j = 0; j < 8; j++) unpack2(P[j], p[2 * j], p[2 * j + 1]);

#define BFLY_STEP(MASK, HALF)                                          \
    {                                                                  \
        bool keepLow = (lane & MASK) == 0;                             \
        _Pragma("unroll")                                              \
        for (int i = 0; i < HALF; i++) {                               \
            float send = keepLow ? p[HALF + i] : p[i];                 \
            float recv = __shfl_xor_sync(0xffffffffu, send, MASK);     \
            p[i] = (keepLow ? p[i] : p[HALF + i]) + recv;              \
        }                                                              \
    }
    BFLY_STEP(1, 8)
    BFLY_STEP(2, 4)
    BFLY_STEP(4, 2)
    BFLY_STEP(8, 1)
#undef BFLY_STEP
    p[0] += __shfl_xor_sync(0xffffffffu, p[0], 16);

    const int c = ((lane & 1) << 3) | ((lane & 2) << 1) |
                  ((lane & 4) >> 1) | ((lane & 8) >> 3);
    float hp2v = p[0];

    float sA = hp2v * A2s[c];
    float dA = hp2v * A2d[c];
#pragma unroll
    for (int mask = 1; mask <= 8; mask <<= 1) {
        sA += __shfl_xor_sync(0xffffffffu, sA, mask);
        dA += __shfl_xor_sync(0xffffffffu, dA, mask);
    }

    if (lane < 16) g_hp2h[(size_t)d * D2 + c] = __float2half_rn(hp2v);
    if (lane == 0) { g_al2s[d] = sA; g_al2d[d] = dA; }
}

// ---------------- layer-2 aggregation + bias + log_softmax ----------------
__global__ __launch_bounds__(256) void kagg2(const float* __restrict__ b2,
                                             float* __restrict__ out) {
    int gw = (blockIdx.x * blockDim.x + threadIdx.x) >> 5;
    if (gw >= NV) return;
    const int d    = gw;
    const int lane = threadIdx.x & 31;
    const int oct  = lane >> 3;
    const int ol   = lane & 7;

    float al2dd = g_al2d[d];
    float accx = 0.f, accy = 0.f, den = 0.f;

    if (oct == 0) {
        float v = g_al2s[d] + al2dd;
        v = (v > 0.f) ? v : 0.2f * v;
        float w = __expf(v);
        den += w;
        float2 hv = __half22float2(*(const __half2*)&g_hp2h[(size_t)d * D2 + 2 * ol]);
        accx = fmaf(hv.x, w, accx);
        accy = fmaf(hv.y, w, accy);
    }

    const int beg = g_off[d], end = g_off[d + 1];
    for (int j = beg; j < end; j += 32) {
        int idx = j + lane;
        int sv  = g_esrc[(idx < end) ? idx : (end - 1)];
        int m   = end - j; if (m > 32) m = 32;
        for (int k = 0; k < m; k += 4) {
            int s0 = __shfl_sync(0xffffffffu, sv, k);
            int s1 = __shfl_sync(0xffffffffu, sv, (k + 1 < m) ? (k + 1) : k);
            int s2 = __shfl_sync(0xffffffffu, sv, (k + 2 < m) ? (k + 2) : k);
            int s3 = __shfl_sync(0xffffffffu, sv, (k + 3 < m) ? (k + 3) : k);
            int s  = (oct == 0) ? s0 : (oct == 1) ? s1 : (oct == 2) ? s2 : s3;
            bool valid = (k + oct) < m;
            if (valid) {
                float v = g_al2s[s] + al2dd;
                v = (v > 0.f) ? v : 0.2f * v;
                float w = __expf(v);
                den += w;
                float2 hv = __half22float2(*(const __half2*)&g_hp2h[(size_t)s * D2 + 2 * ol]);
                accx = fmaf(hv.x, w, accx);
                accy = fmaf(hv.y, w, accy);
            }
        }
    }
    accx += __shfl_xor_sync(0xffffffffu, accx, 8);
    accx += __shfl_xor_sync(0xffffffffu, accx, 16);
    accy += __shfl_xor_sync(0xffffffffu, accy, 8);
    accy += __shfl_xor_sync(0xffffffffu, accy, 16);
    den  += __shfl_xor_sync(0xffffffffu, den, 8);
    den  += __shfl_xor_sync(0xffffffffu, den, 16);

    float v0 = accx / den + b2[2 * ol];
    float v1 = accy / den + b2[2 * ol + 1];
    float mx = fmaxf(v0, v1);
#pragma unroll
    for (int off = 4; off >= 1; off >>= 1)
        mx = fmaxf(mx, __shfl_xor_sync(0xffffffffu, mx, off));
    float se = __expf(v0 - mx) + __expf(v1 - mx);
#pragma unroll
    for (int off = 4; off >= 1; off >>= 1)
        se += __shfl_xor_sync(0xffffffffu, se, off);
    float lse = mx + logf(se);
    if (lane < 8)
        *(float2*)&out[(size_t)d * D2 + 2 * ol] = make_float2(v0 - lse, v1 - lse);
}

// ---------------- launch: two-stream fork/join DAG ----------------
extern "C" void kernel_launch(void* const* d_in, const int* in_sizes, int n_in,
                              void* d_out, int out_size) {
    const float* x   = (const float*)d_in[0];
    const int*   ei  = (const int*)d_in[1];
    const float* W1  = (const float*)d_in[2];
    const float* a1s = (const float*)d_in[3];
    const float* a1d = (const float*)d_in[4];
    const float* b1  = (const float*)d_in[5];
    const float* W2  = (const float*)d_in[6];
    const float* a2s = (const float*)d_in[7];
    const float* a2d = (const float*)d_in[8];
    const float* b2  = (const float*)d_in[9];
    float* out = (float*)d_out;

    const int* src = ei;
    const int* dst = ei + EE;

    static cudaStream_t s1 = 0;
    static cudaEvent_t evFork = 0, evJoin = 0;
    if (!s1) {
        cudaStreamCreateWithFlags(&s1, cudaStreamNonBlocking);
        cudaEventCreateWithFlags(&evFork, cudaEventDisableTiming);
        cudaEventCreateWithFlags(&evJoin, cudaEventDisableTiming);
    }

    cudaEventRecord(evFork, 0);
    cudaStreamWaitEvent(s1, evFork, 0);

    // branch B (s1): CSR build (g_cnt arrives zeroed — kfill countdown invariant)
    khist<<<(EE + 255) / 256, 256, 0, s1>>>(dst);
    kscan12<<<SCAN_NB, 256, 0, s1>>>();
    kscan3<<<SCAN_NB, 256, 0, s1>>>();
    kfill<<<(EE + 255) / 256, 256, 0, s1>>>(src, dst);
    cudaEventRecord(evJoin, s1);

    // branch A (default stream): W split + GEMM1
    kinitW<<<(FIN * D1 + 255) / 256, 256>>>(W1);
    kgemm1<<<(NV + 127) / 128, 256>>>(x, a1s, a1d);

    // join
    cudaStreamWaitEvent(0, evJoin, 0);
    kagg1<<<(NV * 32 + 255) / 256, 256>>>(b1, W2, a2s, a2d);
    kagg2<<<(NV * 32 + 255) / 256, 256>>>(b2, out);
}

// round 14
// speedup vs baseline: 1.1022x; 1.1022x over previous
#include <cuda_runtime.h>
#include <cuda_fp16.h>
#include <math.h>

#define NV  100000
#define EE  1600000
#define FIN 512
#define D1  64
#define H1N 8
#define D2  16
#define SCAN_CH 1024
#define SCAN_NB ((NV + SCAN_CH - 1) / SCAN_CH)   // 98

typedef unsigned long long u64;

// ---- packed f32x2 helpers ----
__device__ __forceinline__ void ffma2(u64& d, u64 a, u64 b) {
    asm("fma.rn.f32x2 %0, %1, %2, %0;" : "+l"(d) : "l"(a), "l"(b));
}
__device__ __forceinline__ u64 pack2(float x, float y) {
    u64 r;
    asm("mov.b64 %0, {%1, %2};" : "=l"(r) : "f"(x), "f"(y));
    return r;
}
__device__ __forceinline__ void unpack2(u64 v, float& x, float& y) {
    asm("mov.b64 {%0, %1}, %2;" : "=f"(x), "=f"(y) : "l"(v));
}

// ---- fp16 MMA helpers ----
__device__ __forceinline__ void ldsm4(unsigned* r, const void* p) {
    unsigned addr = (unsigned)__cvta_generic_to_shared(p);
    asm volatile("ldmatrix.sync.aligned.m8n8.x4.shared.b16 {%0,%1,%2,%3}, [%4];"
                 : "=r"(r[0]), "=r"(r[1]), "=r"(r[2]), "=r"(r[3]) : "r"(addr));
}
__device__ __forceinline__ void mma_f16(float* c, const unsigned* a, const unsigned* b) {
    asm volatile(
        "mma.sync.aligned.m16n8k16.row.col.f32.f16.f16.f32 "
        "{%0,%1,%2,%3}, {%4,%5,%6,%7}, {%8,%9}, {%0,%1,%2,%3};"
        : "+f"(c[0]), "+f"(c[1]), "+f"(c[2]), "+f"(c[3])
        : "r"(a[0]), "r"(a[1]), "r"(a[2]), "r"(a[3]), "r"(b[0]), "r"(b[1]));
}

// ---- scratch (device globals; no allocations allowed) ----
__device__ __half g_hp16[(size_t)NV * D1];   // x @ W1, fp16 (gather payload)
__device__ float  g_al1s[NV * H1N];
__device__ float  g_al1d[NV * H1N];
__device__ __half g_hp2h[(size_t)NV * D2];   // h1 @ W2, fp16 (gather payload)
__device__ float  g_al2s[NV];
__device__ float  g_al2d[NV];
__device__ __half g_W16[D1 * FIN * 2];       // [n][k] hi at k, lo at 512+k
__device__ int    g_cnt[NV];   // INVARIANT: all-zero at launch entry & exit
                               // (khist adds deg, kfill counts back to 0)
__device__ int    g_off[NV + 1];
__device__ int    g_esrc[EE];
__device__ int    g_blk[SCAN_NB];
__device__ int    g_blkoff[SCAN_NB];
__device__ int    g_done;                    // last-block flag (self-resetting)

// ---------------- initW: split W1 into fp16 hi/lo (feeds kgemm1) ------------
__global__ void kinitW(const float* __restrict__ W1) {
    int t = blockIdx.x * blockDim.x + threadIdx.x;
    if (t < FIN * D1) {
        int k = t >> 6, n = t & 63;
        float w = W1[t];
        __half h = __float2half_rn(w);
        float lo = w - __half2float(h);
        g_W16[n * (FIN * 2) + k]       = h;
        g_W16[n * (FIN * 2) + FIN + k] = __float2half_rn(lo);
    }
}

// ---------------- CSR: histogram of dst ----------------
__global__ void khist(const int* __restrict__ dst) {
    int e = blockIdx.x * blockDim.x + threadIdx.x;
    if (e < EE) atomicAdd(&g_cnt[dst[e]], 1);
}

// ---------------- CSR: fused scan stage 1+2 ----------------
__global__ __launch_bounds__(256) void kscan12() {
    __shared__ int wsum[8];
    __shared__ int isLast;
    __shared__ int sm[128];
    int b = blockIdx.x, t = threadIdx.x;
    int base = b * SCAN_CH + t * 4;
    int s = 0;
#pragma unroll
    for (int l = 0; l < 4; l++) s += (base + l < NV) ? g_cnt[base + l] : 0;
#pragma unroll
    for (int off = 16; off >= 1; off >>= 1) s += __shfl_down_sync(0xffffffffu, s, off);
    if ((t & 31) == 0) wsum[t >> 5] = s;
    __syncthreads();
    if (t == 0) {
        int tot = 0;
#pragma unroll
        for (int w = 0; w < 8; w++) tot += wsum[w];
        g_blk[b] = tot;
        __threadfence();
        int v = atomicAdd(&g_done, 1);
        isLast = (v == SCAN_NB - 1);
        if (isLast) g_done = 0;
    }
    __syncthreads();
    if (!isLast) return;
    __threadfence();
    int v = (t < SCAN_NB) ? *(volatile int*)&g_blk[t] : 0;
    if (t < 128) sm[t] = v;
    __syncthreads();
    for (int off = 1; off < 128; off <<= 1) {
        int y = (t >= off && t < 128) ? sm[t - off] : 0;
        __syncthreads();
        if (t < 128) sm[t] += y;
        __syncthreads();
    }
    if (t < SCAN_NB) g_blkoff[t] = sm[t] - v;
}

// ---------------- CSR: scan stage 3 ----------------
__global__ __launch_bounds__(256) void kscan3() {
    __shared__ int wsum[8];
    int b = blockIdx.x, t = threadIdx.x;
    int lane = t & 31, w = t >> 5;
    int base = b * SCAN_CH + t * 4;
    int v[4];
#pragma unroll
    for (int l = 0; l < 4; l++) v[l] = (base + l < NV) ? g_cnt[base + l] : 0;
    int s4 = v[0] + v[1] + v[2] + v[3];
    int x = s4;
#pragma unroll
    for (int off = 1; off < 32; off <<= 1) {
        int y = __shfl_up_sync(0xffffffffu, x, off);
        if (lane >= off) x += y;
    }
    if (lane == 31) wsum[w] = x;
    __syncthreads();
    if (t < 8) {
        int y = wsum[t];
#pragma unroll
        for (int off = 1; off < 8; off <<= 1) {
            int z = __shfl_up_sync(0x000000ffu, y, off);
            if (t >= off) y += z;
        }
        wsum[t] = y;
    }
    __syncthreads();
    int run = g_blkoff[b] + (x - s4) + (w > 0 ? wsum[w - 1] : 0);
#pragma unroll
    for (int l = 0; l < 4; l++) {
        if (base + l < NV) g_off[base + l] = run;
        run += v[l];
    }
    if (b == 0 && t == 0) g_off[NV] = EE;
}

// ---------------- CSR: fill (countdown on g_cnt → restores zeros) -----------
__global__ void kfill(const int* __restrict__ src, const int* __restrict__ dst) {
    int e = blockIdx.x * blockDim.x + threadIdx.x;
    if (e >= EE) return;
    int d = dst[e];
    int slot = atomicAdd(&g_cnt[d], -1) - 1;   // deg-1 .. 0; ends at exactly 0
    g_esrc[g_off[d] + slot] = src[e];
}

// ---------------- GEMM1: 2-term fp16 split MMA + ldmatrix (R12 structure) ---
// hp1 = x @ W1 ≈ xh·Wh + xh·Wl (x rounded to fp16; W kept hi+lo).
// 128x64 block tile, BK=32, 256 threads, fused al1 epilogue, fp16 hp1 output.
__global__ __launch_bounds__(256) void kgemm1(const float* __restrict__ x,
                                              const float* __restrict__ a1s,
                                              const float* __restrict__ a1d) {
    __shared__ __half Ah[128][40];    // hi only, stride 40 (80B: LDSM-conflict-free)
    __shared__ __half Bh[64][72];     // hi|lo, stride 72

    const int tid   = threadIdx.x;
    const int lane  = tid & 31;
    const int wid   = tid >> 5;
    const int g     = lane >> 2;
    const int tg    = lane & 3;
    const int warpM = wid & 3;
    const int warpN = wid >> 2;
    const int row0  = blockIdx.x * 128;

    const int lrow  = lane & 15;
    const int lcolA = (lane >> 4) * 8;
    const int brow  = (lane & 7) + ((lane >> 4) * 8);
    const int bcol  = ((lane >> 3) & 1) * 8;

    float acc[2][4][4];
#pragma unroll
    for (int mi = 0; mi < 2; mi++)
#pragma unroll
        for (int ni = 0; ni < 4; ni++)
#pragma unroll
            for (int q = 0; q < 4; q++) acc[mi][ni][q] = 0.f;

    float4 rx[4];
    uint4  rb[2];
    const float4 z4 = make_float4(0.f, 0.f, 0.f, 0.f);
#pragma unroll
    for (int l = 0; l < 4; l++) {
        int f = l * 256 + tid, r = f >> 3, c4 = (f & 7) * 4, row = row0 + r;
        rx[l] = (row < NV) ? *(const float4*)(x + (size_t)row * FIN + c4) : z4;
    }
#pragma unroll
    for (int l = 0; l < 2; l++) {
        int f = l * 256 + tid, n = f >> 3, q = f & 7;
        int off = n * (FIN * 2) + ((q < 4) ? (q * 8) : (FIN + (q - 4) * 8));
        rb[l] = *(const uint4*)(g_W16 + off);
    }

    for (int kk = 0; kk < FIN; kk += 32) {
#pragma unroll
        for (int l = 0; l < 4; l++) {
            int f = l * 256 + tid, r = f >> 3, c = (f & 7) * 4;
            float4 v = rx[l];
            *(__half2*)&Ah[r][c]     = __floats2half2_rn(v.x, v.y);
            *(__half2*)&Ah[r][c + 2] = __floats2half2_rn(v.z, v.w);
        }
#pragma unroll
        for (int l = 0; l < 2; l++) {
            int f = l * 256 + tid, n = f >> 3, q = f & 7;
            *(uint4*)&Bh[n][q * 8] = rb[l];
        }
        __syncthreads();

        if (kk + 32 < FIN) {
            int kn = kk + 32;
#pragma unroll
            for (int l = 0; l < 4; l++) {
                int f = l * 256 + tid, r = f >> 3, c4 = (f & 7) * 4, row = row0 + r;
                rx[l] = (row < NV) ? *(const float4*)(x + (size_t)row * FIN + kn + c4) : z4;
            }
#pragma unroll
            for (int l = 0; l < 2; l++) {
                int f = l * 256 + tid, n = f >> 3, q = f & 7;
                int off = n * (FIN * 2) + ((q < 4) ? (kn + q * 8) : (FIN + kn + (q - 4) * 8));
                rb[l] = *(const uint4*)(g_W16 + off);
            }
        }

#pragma unroll
        for (int s = 0; s < 2; s++) {
            unsigned ah[2][4], bh[4][2], bl[4][2];
#pragma unroll
            for (int mi = 0; mi < 2; mi++) {
                const __half* pa = &Ah[warpM * 32 + mi * 16 + lrow][s * 16 + lcolA];
                ldsm4(ah[mi], pa);
            }
#pragma unroll
            for (int a = 0; a < 2; a++) {
                const __half* pb = &Bh[warpN * 32 + a * 16 + brow][s * 16 + bcol];
                unsigned t4[4];
                ldsm4(t4, pb);
                bh[2 * a][0] = t4[0]; bh[2 * a][1] = t4[1];
                bh[2 * a + 1][0] = t4[2]; bh[2 * a + 1][1] = t4[3];
                ldsm4(t4, pb + 32);
                bl[2 * a][0] = t4[0]; bl[2 * a][1] = t4[1];
                bl[2 * a + 1][0] = t4[2]; bl[2 * a + 1][1] = t4[3];
            }
#pragma unroll
            for (int mi = 0; mi < 2; mi++)
#pragma unroll
                for (int ni = 0; ni < 4; ni++) {
                    mma_f16(acc[mi][ni], ah[mi], bl[ni]);
                    mma_f16(acc[mi][ni], ah[mi], bh[ni]);
                }
        }
        __syncthreads();
    }

    // epilogue: store hp1 (fp16) + fused attention projections (fp32)
    float2 as2[4], ad2[4];
#pragma unroll
    for (int ni = 0; ni < 4; ni++) {
        int h = warpN * 4 + ni;
        as2[ni] = make_float2(a1s[h * 8 + 2 * tg], a1s[h * 8 + 2 * tg + 1]);
        ad2[ni] = make_float2(a1d[h * 8 + 2 * tg], a1d[h * 8 + 2 * tg + 1]);
    }
#pragma unroll
    for (int mi = 0; mi < 2; mi++)
#pragma unroll
        for (int rh = 0; rh < 2; rh++) {
            int row = row0 + warpM * 32 + mi * 16 + rh * 8 + g;
            bool ok = row < NV;
#pragma unroll
            for (int ni = 0; ni < 4; ni++) {
                float c0 = acc[mi][ni][rh * 2], c1 = acc[mi][ni][rh * 2 + 1];
                if (ok) {
                    int col = warpN * 32 + ni * 8 + 2 * tg;
                    *(__half2*)(g_hp16 + (size_t)row * D1 + col) = __floats2half2_rn(c0, c1);
                }
                float sp = c0 * as2[ni].x + c1 * as2[ni].y;
                float dp = c0 * ad2[ni].x + c1 * ad2[ni].y;
                sp += __shfl_xor_sync(0xffffffffu, sp, 1);
                sp += __shfl_xor_sync(0xffffffffu, sp, 2);
                dp += __shfl_xor_sync(0xffffffffu, dp, 1);
                dp += __shfl_xor_sync(0xffffffffu, dp, 2);
                if (ok && tg == ni) {
                    g_al1s[row * H1N + warpN * 4 + ni] = sp;
                    g_al1d[row * H1N + warpN * 4 + ni] = dp;
                }
            }
        }
}

// ---------------- layer-1 aggregation + FUSED GEMM2 + al2 -------------------
__global__ __launch_bounds__(256) void kagg1(const float* __restrict__ b1,
                                             const float* __restrict__ W2,
                                             const float* __restrict__ a2s,
                                             const float* __restrict__ a2d) {
    __shared__ u64   W2p[D1 * 9];
    __shared__ float A2s[D2], A2d[D2];
    {
        int tid = threadIdx.x;
        for (int i = tid; i < D1 * 8; i += 256) {
            int k = i >> 3, j = i & 7;
            W2p[k * 9 + j] = pack2(W2[k * D2 + 2 * j], W2[k * D2 + 2 * j + 1]);
        }
        if (tid < D2)           A2s[tid] = a2s[tid];
        else if (tid < 2 * D2)  A2d[tid - D2] = a2d[tid - D2];
        __syncthreads();
    }

    int gw = (blockIdx.x * blockDim.x + threadIdx.x) >> 5;
    if (gw >= NV) return;
    const int d    = gw;
    const int lane = threadIdx.x & 31;
    const int grp  = lane >> 3;
    const int gh   = lane & 7;
    const int hsel = lane >> 2;

    const float ald = g_al1d[d * H1N + gh];
    float accx = 0.f, accy = 0.f, den = 0.f;

    {
        float w = 0.f;
        if (grp == 0) {
            float v = g_al1s[d * H1N + gh] + ald;
            v = (v > 0.f) ? v : 0.2f * v;
            w = __expf(v);
            den += w;
        }
        float wl = __shfl_sync(0xffffffffu, w, hsel);
        float2 hv = __half22float2(*(const __half2*)&g_hp16[(size_t)d * D1 + 2 * lane]);
        accx = fmaf(hv.x, wl, accx);
        accy = fmaf(hv.y, wl, accy);
    }

    const int beg = g_off[d], end = g_off[d + 1];
    for (int j = beg; j < end; j += 32) {
        int idx = j + lane;
        int sv  = g_esrc[(idx < end) ? idx : (end - 1)];
        int m   = end - j; if (m > 32) m = 32;
        for (int k = 0; k < m; k += 4) {
            int ke = k + grp;
            int kc = (ke < m) ? ke : (m - 1);
            int s_my = __shfl_sync(0xffffffffu, sv, kc);
            float w = 0.f;
            if (ke < m) {
                float v = g_al1s[s_my * H1N + gh] + ald;
                v = (v > 0.f) ? v : 0.2f * v;
                w = __expf(v);
                den += w;
            }
#pragma unroll
            for (int e = 0; e < 4; e++) {
                int kk  = k + e;
                int kcl = (kk < m) ? kk : (m - 1);
                int s_e = __shfl_sync(0xffffffffu, sv, kcl);
                float wl = __shfl_sync(0xffffffffu, w, e * 8 + hsel);
                float2 hv = __half22float2(
                    *(const __half2*)&g_hp16[(size_t)s_e * D1 + 2 * lane]);
                accx = fmaf(hv.x, wl, accx);
                accy = fmaf(hv.y, wl, accy);
            }
        }
    }

    den += __shfl_xor_sync(0xffffffffu, den, 8);
    den += __shfl_xor_sync(0xffffffffu, den, 16);
    float dl = __shfl_sync(0xffffffffu, den, hsel);

    float v0 = accx / dl + b1[2 * lane];
    float v1 = accy / dl + b1[2 * lane + 1];
    v0 = (v0 > 0.f) ? v0 : expm1f(v0);
    v1 = (v1 > 0.f) ? v1 : expm1f(v1);

    // ---- fused GEMM2 ----
    u64 P[8];
    u64 a0 = pack2(v0, v0), a1 = pack2(v1, v1);
    const u64* w0 = &W2p[(2 * lane) * 9];
    const u64* w1 = &W2p[(2 * lane + 1) * 9];
#pragma unroll
    for (int j = 0; j < 8; j++) {
        P[j] = 0ULL;
        ffma2(P[j], a0, w0[j]);
        ffma2(P[j], a1, w1[j]);
    }
    float p[16];
#pragma unroll
    for (int j = 0; j < 8; j++) unpack2(P[j], p[2 * j], p[2 * j + 1]);

#define BFLY_STEP(MASK, HALF)                                          \
    {                                                                  \
        bool keepLow = (lane & MASK) == 0;                             \
        _Pragma("unroll")                                              \
        for (int i = 0; i < HALF; i++) {                               \
            float send = keepLow ? p[HALF + i] : p[i];                 \
            float recv = __shfl_xor_sync(0xffffffffu, send, MASK);     \
            p[i] = (keepLow ? p[i] : p[HALF + i]) + recv;              \
        }                                                              \
    }
    BFLY_STEP(1, 8)
    BFLY_STEP(2, 4)
    BFLY_STEP(4, 2)
    BFLY_STEP(8, 1)
#undef BFLY_STEP
    p[0] += __shfl_xor_sync(0xffffffffu, p[0], 16);

    const int c = ((lane & 1) << 3) | ((lane & 2) << 1) |
                  ((lane & 4) >> 1) | ((lane & 8) >> 3);
    float hp2v = p[0];

    float sA = hp2v * A2s[c];
    float dA = hp2v * A2d[c];
#pragma unroll
    for (int mask = 1; mask <= 8; mask <<= 1) {
        sA += __shfl_xor_sync(0xffffffffu, sA, mask);
        dA += __shfl_xor_sync(0xffffffffu, dA, mask);
    }

    if (lane < 16) g_hp2h[(size_t)d * D2 + c] = __float2half_rn(hp2v);
    if (lane == 0) { g_al2s[d] = sA; g_al2d[d] = dA; }
}

// ---------------- layer-2 aggregation + bias + log_softmax ----------------
__global__ __launch_bounds__(256) void kagg2(const float* __restrict__ b2,
                                             float* __restrict__ out) {
    int gw = (blockIdx.x * blockDim.x + threadIdx.x) >> 5;
    if (gw >= NV) return;
    const int d    = gw;
    const int lane = threadIdx.x & 31;
    const int oct  = lane >> 3;
    const int ol   = lane & 7;

    float al2dd = g_al2d[d];
    float accx = 0.f, accy = 0.f, den = 0.f;

    if (oct == 0) {
        float v = g_al2s[d] + al2dd;
        v = (v > 0.f) ? v : 0.2f * v;
        float w = __expf(v);
        den += w;
        float2 hv = __half22float2(*(const __half2*)&g_hp2h[(size_t)d * D2 + 2 * ol]);
        accx = fmaf(hv.x, w, accx);
        accy = fmaf(hv.y, w, accy);
    }

    const int beg = g_off[d], end = g_off[d + 1];
    for (int j = beg; j < end; j += 32) {
        int idx = j + lane;
        int sv  = g_esrc[(idx < end) ? idx : (end - 1)];
        int m   = end - j; if (m > 32) m = 32;
        for (int k = 0; k < m; k += 4) {
            int s0 = __shfl_sync(0xffffffffu, sv, k);
            int s1 = __shfl_sync(0xffffffffu, sv, (k + 1 < m) ? (k + 1) : k);
            int s2 = __shfl_sync(0xffffffffu, sv, (k + 2 < m) ? (k + 2) : k);
            int s3 = __shfl_sync(0xffffffffu, sv, (k + 3 < m) ? (k + 3) : k);
            int s  = (oct == 0) ? s0 : (oct == 1) ? s1 : (oct == 2) ? s2 : s3;
            bool valid = (k + oct) < m;
            if (valid) {
                float v = g_al2s[s] + al2dd;
                v = (v > 0.f) ? v : 0.2f * v;
                float w = __expf(v);
                den += w;
                float2 hv = __half22float2(*(const __half2*)&g_hp2h[(size_t)s * D2 + 2 * ol]);
                accx = fmaf(hv.x, w, accx);
                accy = fmaf(hv.y, w, accy);
            }
        }
    }
    accx += __shfl_xor_sync(0xffffffffu, accx, 8);
    accx += __shfl_xor_sync(0xffffffffu, accx, 16);
    accy += __shfl_xor_sync(0xffffffffu, accy, 8);
    accy += __shfl_xor_sync(0xffffffffu, accy, 16);
    den  += __shfl_xor_sync(0xffffffffu, den, 8);
    den  += __shfl_xor_sync(0xffffffffu, den, 16);

    float v0 = accx / den + b2[2 * ol];
    float v1 = accy / den + b2[2 * ol + 1];
    float mx = fmaxf(v0, v1);
#pragma unroll
    for (int off = 4; off >= 1; off >>= 1)
        mx = fmaxf(mx, __shfl_xor_sync(0xffffffffu, mx, off));
    float se = __expf(v0 - mx) + __expf(v1 - mx);
#pragma unroll
    for (int off = 4; off >= 1; off >>= 1)
        se += __shfl_xor_sync(0xffffffffu, se, off);
    float lse = mx + logf(se);
    if (lane < 8)
        *(float2*)&out[(size_t)d * D2 + 2 * ol] = make_float2(v0 - lse, v1 - lse);
}

// ---------------- launch: two-stream fork/join DAG ----------------
extern "C" void kernel_launch(void* const* d_in, const int* in_sizes, int n_in,
                              void* d_out, int out_size) {
    const float* x   = (const float*)d_in[0];
    const int*   ei  = (const int*)d_in[1];
    const float* W1  = (const float*)d_in[2];
    const float* a1s = (const float*)d_in[3];
    const float* a1d = (const float*)d_in[4];
    const float* b1  = (const float*)d_in[5];
    const float* W2  = (const float*)d_in[6];
    const float* a2s = (const float*)d_in[7];
    const float* a2d = (const float*)d_in[8];
    const float* b2  = (const float*)d_in[9];
    float* out = (float*)d_out;

    const int* src = ei;
    const int* dst = ei + EE;

    static cudaStream_t s1 = 0;
    static cudaEvent_t evFork = 0, evJoin = 0;
    if (!s1) {
        cudaStreamCreateWithFlags(&s1, cudaStreamNonBlocking);
        cudaEventCreateWithFlags(&evFork, cudaEventDisableTiming);
        cudaEventCreateWithFlags(&evJoin, cudaEventDisableTiming);
    }

    cudaEventRecord(evFork, 0);
    cudaStreamWaitEvent(s1, evFork, 0);

    // branch B (s1): CSR build (g_cnt arrives zeroed — kfill countdown invariant)
    khist<<<(EE + 255) / 256, 256, 0, s1>>>(dst);
    kscan12<<<SCAN_NB, 256, 0, s1>>>();
    kscan3<<<SCAN_NB, 256, 0, s1>>>();
    kfill<<<(EE + 255) / 256, 256, 0, s1>>>(src, dst);
    cudaEventRecord(evJoin, s1);

    // branch A (default stream): W split + GEMM1
    kinitW<<<(FIN * D1 + 255) / 256, 256>>>(W1);
    kgemm1<<<(NV + 127) / 128, 256>>>(x, a1s, a1d);

    // join
    cudaStreamWaitEvent(0, evJoin, 0);
    kagg1<<<(NV * 32 + 255) / 256, 256>>>(b1, W2, a2s, a2d);
    kagg2<<<(NV * 32 + 255) / 256, 256>>>(b2, out);
}